// round 2
// baseline (speedup 1.0000x reference)
#include <cuda_runtime.h>
#include <cstdint>

#define NPTS  5760
#define BATCH 4
#define CT    640            // columns per tile
#define NCT   9              // 5760 / 640
#define RT    240            // rows per block
#define NRT   24             // 5760 / 240
#define WARPS 8
#define TPB   256
#define RPW   30             // rows per warp (240 / 8)
#define EPL   20             // elements per lane (640 / 32)
#define TEMPF 100.0f
#define NEGV  -1e30f
#define TH_OFF 0.30f         // exp cutoff: e^(-30) ~ 1e-13 relative

// -------- scratch (static device globals; no allocation allowed) --------
__device__ float g_rowpart[BATCH * NCT * NPTS * 8];   // per (b,tile,row): m,s,px,py,pz,argcol
__device__ float g_colV[BATCH * NRT * NPTS];          // per (b,rowtile,col): best value
__device__ int   g_colR[BATCH * NRT * NPTS];          // per (b,rowtile,col): best row
__device__ float g_p2[BATCH * NPTS * 4];              // points2 (xyz, pad)
__device__ int   g_i21[BATCH * NPTS];                 // ind2to1
__device__ int   g_i12[BATCH * NPTS];                 // ind1to2
__device__ float g_loss[BATCH];

// ================= K1: single pass over match_vals (valid rows only) ========
__global__ void __launch_bounds__(TPB, 2) k_main(const float* __restrict__ match,
                                                 const float* __restrict__ tgt,
                                                 const int*   __restrict__ pmask)
{
    const int b    = blockIdx.z;
    const int tile = blockIdx.x;
    const int rt   = blockIdx.y;
    const int warp = threadIdx.x >> 5;
    const int lane = threadIdx.x & 31;
    const int col0 = tile * CT;
    const int row0 = rt * RT;

    const int* m1p = pmask + (size_t)(2 * b) * NPTS;
    const int* m2p = pmask + (size_t)(2 * b + 1) * NPTS;

    // per-lane column mask-add (m2): +0 if valid, -1e30 if masked (exact NEG in f32)
    float ma[EPL];
    float cbv[EPL];   // column-best value (raw v, m1-gated by row skipping)
    int   cbr[EPL];   // column-best row
#pragma unroll
    for (int k = 0; k < 5; k++) {
        int4 mm = *(const int4*)(m2p + col0 + k * 128 + lane * 4);
        ma[4*k+0] = mm.x ? 0.f : NEGV;
        ma[4*k+1] = mm.y ? 0.f : NEGV;
        ma[4*k+2] = mm.z ? 0.f : NEGV;
        ma[4*k+3] = mm.w ? 0.f : NEGV;
    }
#pragma unroll
    for (int e = 0; e < EPL; e++) { cbv[e] = -INFINITY; cbr[e] = 0; }

    const float* tgx = tgt + (size_t)(b * 3 + 0) * NPTS;
    const float* tgy = tgt + (size_t)(b * 3 + 1) * NPTS;
    const float* tgz = tgt + (size_t)(b * 3 + 2) * NPTS;

    const int rbeg = row0 + warp * RPW;
    // preload validity of this warp's 30 rows into a ballot mask
    bool vb = false;
    if (lane < RPW) vb = (m1p[rbeg + lane] != 0);
    const unsigned mbits = __ballot_sync(0xffffffffu, vb);

    for (int rr = 0; rr < RPW; rr++) {
        if (!((mbits >> rr) & 1u)) continue;     // skip !m1 rows entirely (halves traffic)
        const int r = rbeg + rr;
        const float* rp = match + ((size_t)b * NPTS + r) * NPTS + col0;
        float v[EPL];
#pragma unroll
        for (int k = 0; k < 5; k++) {
            float4 t = __ldcs((const float4*)(rp + k * 128 + lane * 4));
            v[4*k+0] = t.x; v[4*k+1] = t.y; v[4*k+2] = t.z; v[4*k+3] = t.w;
        }
        // sweep: column-best (raw v) + lane max of masked value
        float lm = -INFINITY;
#pragma unroll
        for (int e = 0; e < EPL; e++) {
            if (v[e] > cbv[e]) { cbv[e] = v[e]; cbr[e] = r; }
            lm = fmaxf(lm, v[e] + ma[e]);
        }
        // warp tile-max
        float wm = lm;
#pragma unroll
        for (int o = 16; o; o >>= 1) wm = fmaxf(wm, __shfl_xor_sync(0xffffffffu, wm, o));
        const float th = wm - TH_OFF;
        float s = 0.f, px = 0.f, py = 0.f, pz = 0.f;
        int bc = 0x7fffffff;
        if (lm > th) {    // rare lanes only -> almost no MUFU traffic
#pragma unroll
            for (int e = 0; e < EPL; e++) {
                float vm = v[e] + ma[e];
                if (vm > th) {
                    float w = __expf((vm - wm) * TEMPF);
                    int c = col0 + (e >> 2) * 128 + lane * 4 + (e & 3);
                    s  += w;
                    px += w * tgx[c];
                    py += w * tgy[c];
                    pz += w * tgz[c];
                    if (vm == wm) bc = min(bc, c);   // first-index tie-break within tile
                }
            }
        }
#pragma unroll
        for (int o = 16; o; o >>= 1) {
            s  += __shfl_xor_sync(0xffffffffu, s,  o);
            px += __shfl_xor_sync(0xffffffffu, px, o);
            py += __shfl_xor_sync(0xffffffffu, py, o);
            pz += __shfl_xor_sync(0xffffffffu, pz, o);
            bc  = min(bc, __shfl_xor_sync(0xffffffffu, bc, o));
        }
        if (lane == 0) {
            float* out = g_rowpart + ((size_t)(b * NCT + tile) * NPTS + r) * 8;
            *(float4*)(out)     = make_float4(wm, s, px, py);
            *(float4*)(out + 4) = make_float4(pz, __int_as_float(bc), 0.f, 0.f);
        }
    }

    // block-level column-best merge (warps in row order => first-row tie-break)
    __shared__ float sv[WARPS][CT];
    __shared__ int   sr[WARPS][CT];
#pragma unroll
    for (int e = 0; e < EPL; e++) {
        int cl = (e >> 2) * 128 + lane * 4 + (e & 3);
        sv[warp][cl] = cbv[e];
        sr[warp][cl] = cbr[e];
    }
    __syncthreads();
    for (int c = threadIdx.x; c < CT; c += TPB) {
        float bv = -INFINITY; int br = 0;
#pragma unroll
        for (int w = 0; w < WARPS; w++) {
            float vv = sv[w][c];
            if (vv > bv) { bv = vv; br = sr[w][c]; }
        }
        size_t o = (size_t)(b * NRT + rt) * NPTS + col0 + c;
        g_colV[o] = bv;
        g_colR[o] = br;
    }
}

// ================= K2: merge row tiles (softmax + argmax) and column tiles ==
__global__ void k_merge(const int* __restrict__ pmask)
{
    const int gid = blockIdx.x * blockDim.x + threadIdx.x;
    const int total = BATCH * NPTS;
    if (gid < total) {
        const int b = gid / NPTS, r = gid - b * NPTS;
        if (!pmask[(size_t)(2 * b) * NPTS + r]) return;   // skipped rows never read
        float4 A[NCT], Bv[NCT];
#pragma unroll
        for (int t = 0; t < NCT; t++) {
            const float* base = g_rowpart + ((size_t)(b * NCT + t) * NPTS + r) * 8;
            A[t]  = *(const float4*)(base);
            Bv[t] = *(const float4*)(base + 4);
        }
        float M = -INFINITY; int argc = 0;
#pragma unroll
        for (int t = 0; t < NCT; t++)
            if (A[t].x > M) { M = A[t].x; argc = __float_as_int(Bv[t].y); }
        float S = 0.f, Px = 0.f, Py = 0.f, Pz = 0.f;
#pragma unroll
        for (int t = 0; t < NCT; t++) {
            float w = __expf((A[t].x - M) * TEMPF);
            S  += A[t].y * w;
            Px += A[t].z * w;
            Py += A[t].w * w;
            Pz += Bv[t].x * w;
        }
        float inv = 1.f / S;
        *(float4*)(g_p2 + (size_t)gid * 4) = make_float4(Px * inv, Py * inv, Pz * inv, 0.f);
        g_i21[gid] = argc;
    } else if (gid < 2 * total) {
        const int g2 = gid - total;
        const int b = g2 / NPTS, c = g2 - b * NPTS;
        float bv = -INFINITY; int br = 0;
        for (int t = 0; t < NRT; t++) {
            size_t o = (size_t)(b * NRT + t) * NPTS + c;
            float vv = g_colV[o];
            if (vv > bv) { bv = vv; br = g_colR[o]; }
        }
        g_i12[g2] = br;
    }
}

// ================= K3: per-batch loss ========================================
__global__ void __launch_bounds__(TPB) k_loss(const float* __restrict__ src,
                                              const float* __restrict__ wts,
                                              const float* __restrict__ Tiv,
                                              const int*   __restrict__ pmask)
{
    const int b = blockIdx.x;
    __shared__ float T21[12];
    if (threadIdx.x == 0) {
        const float* Ts = Tiv + (size_t)(2 * b) * 16;
        const float* Tt = Tiv + (size_t)(2 * b + 1) * 16;
        // A = se3_inv(Tt): A[i][k]=Tt[k][i] (k<3), A[i][3] = -(Tt[:,i] . Tt[:,3])
        float A[3][4];
        for (int i = 0; i < 3; i++) {
            for (int k = 0; k < 3; k++) A[i][k] = Tt[k * 4 + i];
            A[i][3] = -(Tt[0 * 4 + i] * Tt[3] + Tt[1 * 4 + i] * Tt[7] + Tt[2 * 4 + i] * Tt[11]);
        }
        // T21 = A @ Ts, rows 0..2 (Ts row 3 matters: Ts is a general 4x4)
        for (int i = 0; i < 3; i++)
            for (int j = 0; j < 4; j++)
                T21[i * 4 + j] = A[i][0] * Ts[j] + A[i][1] * Ts[4 + j]
                               + A[i][2] * Ts[8 + j] + A[i][3] * Ts[12 + j];
    }
    __syncthreads();

    const float* sx = src + (size_t)(b * 3 + 0) * NPTS;
    const float* sy = src + (size_t)(b * 3 + 1) * NPTS;
    const float* sz = src + (size_t)(b * 3 + 2) * NPTS;
    const float* w0 = wts + (size_t)(b * 6 + 0) * NPTS;
    const float* w1 = wts + (size_t)(b * 6 + 1) * NPTS;
    const float* w2 = wts + (size_t)(b * 6 + 2) * NPTS;
    const float* w3 = wts + (size_t)(b * 6 + 3) * NPTS;
    const float* w4 = wts + (size_t)(b * 6 + 4) * NPTS;
    const float* w5 = wts + (size_t)(b * 6 + 5) * NPTS;
    const int*   m1  = pmask + (size_t)(2 * b) * NPTS;
    const int*   i21 = g_i21 + b * NPTS;
    const int*   i12 = g_i12 + b * NPTS;

    float sm = 0.f, sd = 0.f, cnt = 0.f;
    for (int i = threadIdx.x; i < NPTS; i += TPB) {
        if (!m1[i]) continue;
        int j = i21[i];
        if (i12[j] != i) continue;                      // consist check
        float p0 = sx[i], p1 = sy[i], p2v = sz[i];
        float q0 = T21[0] * p0 + T21[1] * p1 + T21[2]  * p2v + T21[3];
        float q1 = T21[4] * p0 + T21[5] * p1 + T21[6]  * p2v + T21[7];
        float q2 = T21[8] * p0 + T21[9] * p1 + T21[10] * p2v + T21[11];
        float4 pp = *(const float4*)(g_p2 + (size_t)(b * NPTS + i) * 4);
        float e0 = q0 - pp.x, e1 = q1 - pp.y, e2 = q2 - pp.z;
        float aa = w0[i], bb = w1[i], cc = w2[i];
        float d0 = w3[i], d1 = w4[i], d2 = w5[i];
        // e^T (L diag(e^d) L^T) e  =  sum_k e^{d_k} ((L^T e)_k)^2
        float u0 = e0 + aa * e1 + bb * e2;
        float u1 = e1 + cc * e2;
        float u2 = e2;
        float mah = __expf(d0) * u0 * u0 + __expf(d1) * u1 * u1 + __expf(d2) * u2 * u2;
        if (mah < 10000.0f) { sm += mah; sd += d0 + d1 + d2; cnt += 1.f; }
    }
#pragma unroll
    for (int o = 16; o; o >>= 1) {
        sm  += __shfl_xor_sync(0xffffffffu, sm,  o);
        sd  += __shfl_xor_sync(0xffffffffu, sd,  o);
        cnt += __shfl_xor_sync(0xffffffffu, cnt, o);
    }
    __shared__ float rs[WARPS], rd[WARPS], rc[WARPS];
    if ((threadIdx.x & 31) == 0) {
        rs[threadIdx.x >> 5] = sm;
        rd[threadIdx.x >> 5] = sd;
        rc[threadIdx.x >> 5] = cnt;
    }
    __syncthreads();
    if (threadIdx.x == 0) {
        float S = 0.f, D = 0.f, C = 0.f;
        for (int w = 0; w < WARPS; w++) { S += rs[w]; D += rd[w]; C += rc[w]; }
        g_loss[b] = (S - D) / fmaxf(C, 1.f);
    }
}

// ================= K4: final sum =============================================
__global__ void k_final(float* __restrict__ out)
{
    if (threadIdx.x == 0)
        out[0] = g_loss[0] + g_loss[1] + g_loss[2] + g_loss[3];
}

// ================= launch ====================================================
extern "C" void kernel_launch(void* const* d_in, const int* in_sizes, int n_in,
                              void* d_out, int out_size)
{
    const float* src   = (const float*)d_in[0];   // (4,3,5760)
    const float* tgt   = (const float*)d_in[1];   // (4,3,5760)
    const float* wts   = (const float*)d_in[2];   // (4,6,5760)
    const float* match = (const float*)d_in[3];   // (4,5760,5760)
    const float* Tiv   = (const float*)d_in[4];   // (8,4,4)
    const int*   pmask = (const int*)d_in[5];     // (8,5760)

    dim3 g1(NCT, NRT, BATCH);                     // 9 x 24 x 4 = 864 blocks
    k_main<<<g1, TPB>>>(match, tgt, pmask);
    k_merge<<<(2 * BATCH * NPTS + 255) / 256, 256>>>(pmask);
    k_loss<<<BATCH, TPB>>>(src, wts, Tiv, pmask);
    k_final<<<1, 32>>>((float*)d_out);
}